// round 11
// baseline (speedup 1.0000x reference)
#include <cuda_runtime.h>

// Problem constants (fixed by the reference)
#define N_SAE  128
#define D_DATA 128
#define D_DICT 512
#define BATCH  1024
#define CHUNK  8      // tokens per compute CTA
#define NCHUNK 6      // grid.y; cap = 48 tokens/expert

typedef unsigned long long u64;
typedef unsigned int u32;

// Cross-CTA combine state (MONOTONIC across graph replays; never reset).
__device__ float g_stage[BATCH * D_DATA];
__device__ int   g_arr  [BATCH];
__device__ int   g_ready[BATCH];

// ---------------- helpers ----------------
__device__ __forceinline__ u64 pk(float lo, float hi) {
    u64 r; asm("mov.b64 %0,{%1,%2};" : "=l"(r) : "f"(lo), "f"(hi)); return r;
}
__device__ __forceinline__ void upk(float& lo, float& hi, u64 v) {
    asm("mov.b64 {%0,%1},%2;" : "=f"(lo), "=f"(hi) : "l"(v));
}
__device__ __forceinline__ u64 add2(u64 a, u64 b) {
    u64 d; asm("add.rn.f32x2 %0,%1,%2;" : "=l"(d) : "l"(a), "l"(b)); return d;
}
// Round-to-nearest tf32 (unbiased).
__device__ __forceinline__ u32 tf32r(float f) {
    u32 r; asm("cvt.rna.tf32.f32 %0,%1;" : "=r"(r) : "f"(f)); return r;
}
__device__ __forceinline__ void mma_tf32(float& c0, float& c1, float& c2, float& c3,
                                         u32 a0, u32 a1, u32 a2, u32 a3,
                                         u32 b0, u32 b1) {
    asm("mma.sync.aligned.m16n8k8.row.col.f32.tf32.tf32.f32 "
        "{%0,%1,%2,%3},{%4,%5,%6,%7},{%8,%9},{%0,%1,%2,%3};"
        : "+f"(c0), "+f"(c1), "+f"(c2), "+f"(c3)
        : "r"(a0), "r"(a1), "r"(a2), "r"(a3), "r"(b0), "r"(b1));
}
// tf32-round a float4 and store to 16B-aligned smem.
__device__ __forceinline__ void sts4(float* dst, float4 v) {
    float4 w;
    w.x = __uint_as_float(tf32r(v.x));
    w.y = __uint_as_float(tf32r(v.y));
    w.z = __uint_as_float(tf32r(v.z));
    w.w = __uint_as_float(tf32r(v.w));
    *(float4*)dst = w;
}

// Dynamic smem layout (float units). Row pads 520/136: bank = (8t+g+c) mod 32
// across a fragment -> conflict-free LDS; rows stay 16B-aligned for STS.128.
#define ENC_ROW 520                        // 512 e + pad
#define DEC_ROW 136                        // 128 d + pad
#define ENC_BUF (8 * ENC_ROW)              // 4160 floats per buffer
#define DEC_HALF (8 * DEC_ROW)             // 1088 floats per K-half slice
#define DEC_BUF (2 * DEC_HALF)             // 2176 floats per buffer
#define OFF_WBUF 0                          // 2*ENC_BUF = 8320 (dec aliases: 2*DEC_BUF=4352)
#define OFF_XS   (2 * ENC_BUF)             // 8320:  xs  [128][8]
#define OFF_ACTS (OFF_XS + D_DATA * CHUNK) // 9344:  acts[512][8]
#define OFF_PART (OFF_ACTS + D_DICT * CHUNK) // 13440: part[2][4][128] u64
#define SMEM_FLOATS (OFF_PART + 2 * 4 * D_DATA * 2)
#define SMEM_BYTES (SMEM_FLOATS * 4)       // 61952 B -> 3 CTAs/SM fits 228KB

// ---------------------------------------------------------------------------
// Single fused kernel: routing scan + tf32-MMA encode/decode with smem-staged
// double-buffered weight tiles + lock-free cross-CTA combine.
// grid = (N_SAE, NCHUNK), 512 threads (16 warps).
// ---------------------------------------------------------------------------
__global__ void __launch_bounds__(512, 3)
k_compute(const float* __restrict__ x,
          const float* __restrict__ gate,
          const float* __restrict__ Wenc,
          const float* __restrict__ Wdec,
          const float* __restrict__ benc,
          const float* __restrict__ bdec,
          float* __restrict__ out) {
    int s = blockIdx.x;
    int t0 = blockIdx.y * CHUNK;

    extern __shared__ __align__(16) float smf[];
    float* wbuf = smf + OFF_WBUF;
    float* xs   = smf + OFF_XS;
    float* acts = smf + OFF_ACTS;
    u64*   part = (u64*)(smf + OFF_PART);

    __shared__ float gsf[CHUNK];
    __shared__ int prtok[CHUNK];
    __shared__ int sarr[CHUNK];
    __shared__ unsigned masks[32];
    __shared__ int pcnt[32];
    __shared__ int ntot;

    int tid  = threadIdx.x;
    int warp = tid >> 5, lane = tid & 31;
    int g = lane >> 2, t = lane & 3;        // mma fragment coords

    // ---- Routing: column scan of gate[:, s] (proven) ----
    float v0 = __ldg(&gate[(size_t)tid * N_SAE + s]);
    float v1 = __ldg(&gate[(size_t)(tid + 512) * N_SAE + s]);
    unsigned m0 = __ballot_sync(0xffffffffu, v0 != 0.0f);
    unsigned m1 = __ballot_sync(0xffffffffu, v1 != 0.0f);
    if (lane == 0) { masks[warp] = m0; masks[16 + warp] = m1; }
    if (tid < CHUNK) { prtok[tid] = 0; gsf[tid] = 0.0f; }
    __syncthreads();
    if (warp == 0) {
        int c = __popc(masks[lane]);
        int ex = c;
        #pragma unroll
        for (int o = 1; o < 32; o <<= 1) {
            int tt = __shfl_up_sync(0xffffffffu, ex, o);
            if (lane >= o) ex += tt;
        }
        pcnt[lane] = ex - c;
        if (lane == 31) ntot = ex;
    }
    __syncthreads();
    int n = ntot;
    if (t0 >= n) return;
    int m = n - t0; if (m > CHUNK) m = CHUNK;

    if (v0 != 0.0f) {
        int r = pcnt[warp] + __popc(m0 & ((1u << lane) - 1));
        if (r >= t0 && r < t0 + CHUNK) { prtok[r - t0] = tid; gsf[r - t0] = v0; }
    }
    if (v1 != 0.0f) {
        int r = pcnt[16 + warp] + __popc(m1 & ((1u << lane) - 1));
        if (r >= t0 && r < t0 + CHUNK) { prtok[r - t0] = tid + 512; gsf[r - t0] = v1; }
    }
    __syncthreads();

    // ---- xs[d][tok], tf32-rounded ----
    for (int i = tid; i < D_DATA * CHUNK; i += 512) {
        int j = i >> 7, d = i & 127;
        float v = (j < m) ? x[(size_t)prtok[j] * D_DATA + d] : 0.0f;
        xs[d * CHUNK + j] = __uint_as_float(tf32r(v));
    }

    // ================= Encode =================
    // C[512e, 8tok] = Wenc^T @ x^T. Warp w: e-band [32w, 32w+32), 16 k-steps.
    // Weight k-slice [8d x 512e] staged to smem each step (double-buffered).
    float c00, c01, c02, c03, c10, c11, c12, c13;
    {
        const float4* W4 = (const float4*)(Wenc + (size_t)s * D_DATA * D_DICT);
        int dl = tid >> 7;            // 0..3 (this thread stages rows dl, dl+4)
        int e4 = tid & 127;           // float4 col
        float4 p0 = __ldg(&W4[(dl    ) * 128 + e4]);
        float4 p1 = __ldg(&W4[(dl + 4) * 128 + e4]);
        sts4(wbuf + (dl    ) * ENC_ROW + e4 * 4, p0);
        sts4(wbuf + (dl + 4) * ENC_ROW + e4 * 4, p1);
        __syncthreads();              // slice 0 + xs visible

        int e0 = warp * 32;
        c00 = c01 = c02 = c03 = c10 = c11 = c12 = c13 = 0.0f;
        for (int ks = 0; ks < 16; ks++) {
            int cur = ks & 1;
            if (ks < 15) {
                p0 = __ldg(&W4[((ks + 1) * 8 + dl    ) * 128 + e4]);
                p1 = __ldg(&W4[((ks + 1) * 8 + dl + 4) * 128 + e4]);
            }
            const float* bw = wbuf + cur * ENC_BUF;
            u32 a00 = __float_as_uint(bw[(t    ) * ENC_ROW + e0 + g     ]);
            u32 a01 = __float_as_uint(bw[(t    ) * ENC_ROW + e0 + g +  8]);
            u32 a02 = __float_as_uint(bw[(t + 4) * ENC_ROW + e0 + g     ]);
            u32 a03 = __float_as_uint(bw[(t + 4) * ENC_ROW + e0 + g +  8]);
            u32 a10 = __float_as_uint(bw[(t    ) * ENC_ROW + e0 + g + 16]);
            u32 a11 = __float_as_uint(bw[(t    ) * ENC_ROW + e0 + g + 24]);
            u32 a12 = __float_as_uint(bw[(t + 4) * ENC_ROW + e0 + g + 16]);
            u32 a13 = __float_as_uint(bw[(t + 4) * ENC_ROW + e0 + g + 24]);
            u32 b0 = __float_as_uint(xs[(8 * ks + t    ) * CHUNK + g]);
            u32 b1 = __float_as_uint(xs[(8 * ks + t + 4) * CHUNK + g]);
            mma_tf32(c00, c01, c02, c03, a00, a01, a02, a03, b0, b1);
            mma_tf32(c10, c11, c12, c13, a10, a11, a12, a13, b0, b1);
            if (ks < 15) {
                float* nb = wbuf + (1 - cur) * ENC_BUF;
                sts4(nb + (dl    ) * ENC_ROW + e4 * 4, p0);
                sts4(nb + (dl + 4) * ENC_ROW + e4 * 4, p1);
            }
            __syncthreads();
        }

        // bias + relu + gate + tf32-round -> acts[e][tok]
        int e0w = warp * 32;
        float gt0 = gsf[2 * t], gt1 = gsf[2 * t + 1];
        #pragma unroll
        for (int tau = 0; tau < 2; tau++) {
            int e = e0w + 16 * tau + g;
            float bg  = benc[(size_t)s * D_DICT + e];
            float bg8 = benc[(size_t)s * D_DICT + e + 8];
            float q0 = tau ? c10 : c00, q1 = tau ? c11 : c01;
            float q2 = tau ? c12 : c02, q3 = tau ? c13 : c03;
            acts[(e    ) * CHUNK + 2 * t    ] = __uint_as_float(tf32r(fmaxf(q0 + bg , 0.f) * gt0));
            acts[(e    ) * CHUNK + 2 * t + 1] = __uint_as_float(tf32r(fmaxf(q1 + bg , 0.f) * gt1));
            acts[(e + 8) * CHUNK + 2 * t    ] = __uint_as_float(tf32r(fmaxf(q2 + bg8, 0.f) * gt0));
            acts[(e + 8) * CHUNK + 2 * t + 1] = __uint_as_float(tf32r(fmaxf(q3 + bg8, 0.f) * gt1));
        }
    }

    // ================= Decode =================
    // C[128d, 8tok] = Wdec^T @ acts. Warp: m-tile d0=16*(w&7), K-half w>>3.
    // Slice-pair [2 halves x 8e x 128d] staged per step (aliases enc buffers).
    {
        const float4* W4 = (const float4*)(Wdec + (size_t)s * D_DICT * D_DATA);
        int hq = tid >> 8;            // staging half
        int el = (tid >> 5) & 7;      // staging e-row in slice
        int d4 = tid & 31;            // float4 col
        float4 q0 = __ldg(&W4[(hq * 256 + el) * 32 + d4]);
        sts4(wbuf + hq * DEC_HALF + el * DEC_ROW + d4 * 4, q0);
        __syncthreads();              // acts + dec slice 0 visible

        int d0   = (warp & 7) * 16;
        int half = warp >> 3;
        float c0 = 0, c1 = 0, c2 = 0, c3 = 0;
        for (int ks = 0; ks < 32; ks++) {
            int cur = ks & 1;
            if (ks < 31) q0 = __ldg(&W4[(hq * 256 + (ks + 1) * 8 + el) * 32 + d4]);
            const float* bw = wbuf + cur * DEC_BUF + half * DEC_HALF;
            u32 a0 = __float_as_uint(bw[(t    ) * DEC_ROW + d0 + g    ]);
            u32 a1 = __float_as_uint(bw[(t    ) * DEC_ROW + d0 + g + 8]);
            u32 a2 = __float_as_uint(bw[(t + 4) * DEC_ROW + d0 + g    ]);
            u32 a3 = __float_as_uint(bw[(t + 4) * DEC_ROW + d0 + g + 8]);
            u32 b0 = __float_as_uint(acts[(half * 256 + 8 * ks + t    ) * CHUNK + g]);
            u32 b1 = __float_as_uint(acts[(half * 256 + 8 * ks + t + 4) * CHUNK + g]);
            mma_tf32(c0, c1, c2, c3, a0, a1, a2, a3, b0, b1);
            if (ks < 31)
                sts4(wbuf + (1 - cur) * DEC_BUF + hq * DEC_HALF + el * DEC_ROW + d4 * 4, q0);
            __syncthreads();
        }
        // part[half][token-pair t][d] = pk(tok 2t, tok 2t+1)
        part[half * 512 + t * 128 + d0 + g    ] = pk(c0, c1);
        part[half * 512 + t * 128 + d0 + g + 8] = pk(c2, c3);
    }
    __syncthreads();

    // ---- Epilogue: reduce 2 K-halves + b_dec, then PROVEN lock-free combine ----
    {
        int d  = tid & 127;
        int tp = tid >> 7;         // token pair: tokens 2tp (lo), 2tp+1 (hi)
        u64 sum = add2(part[0 * 512 + tp * 128 + d], part[1 * 512 + tp * 128 + d]);
        float lo, hi; upk(lo, hi, sum);
        float bd = bdec[(size_t)s * D_DATA + d];
        float v[2]; v[0] = lo + bd; v[1] = hi + bd;

        if (tid < CHUNK) sarr[tid] = (tid < m) ? atomicAdd(&g_arr[prtok[tid]], 1) : 0;
        __syncthreads();

        #pragma unroll
        for (int q = 0; q < 2; q++) {
            int j = 2 * tp + q;
            if (j < m && (sarr[j] & 1) == 0)
                __stcg(&g_stage[(size_t)prtok[j] * D_DATA + d], v[q]);
        }
        __syncthreads();

        if (tid < m && (sarr[tid] & 1) == 0) {
            __threadfence();
            atomicAdd(&g_ready[prtok[tid]], 1);
        }

        if (tid < m && (sarr[tid] & 1) == 1) {
            int b = prtok[tid];
            int want = (sarr[tid] >> 1) + 1;
            while (atomicAdd(&g_ready[b], 0) < want) {}
            __threadfence();
        }
        __syncthreads();

        #pragma unroll
        for (int q = 0; q < 2; q++) {
            int j = 2 * tp + q;
            if (j < m && (sarr[j] & 1) == 1) {
                int b = prtok[j];
                float other = __ldcg(&g_stage[(size_t)b * D_DATA + d]);
                out[(size_t)b * D_DATA + d] = v[q] + other;
            }
        }
    }
}

// ---------------------------------------------------------------------------
// Launch. Inputs (metadata order): x, gate, W_enc, W_dec, b_enc, b_dec, k
// ---------------------------------------------------------------------------
extern "C" void kernel_launch(void* const* d_in, const int* in_sizes, int n_in,
                              void* d_out, int out_size) {
    const float* x    = (const float*)d_in[0];
    const float* gate = (const float*)d_in[1];
    const float* Wenc = (const float*)d_in[2];
    const float* Wdec = (const float*)d_in[3];
    const float* benc = (const float*)d_in[4];
    const float* bdec = (const float*)d_in[5];
    float* out = (float*)d_out;

    cudaFuncSetAttribute(k_compute, cudaFuncAttributeMaxDynamicSharedMemorySize,
                         SMEM_BYTES);

    dim3 grid(N_SAE, NCHUNK);
    k_compute<<<grid, 512, SMEM_BYTES>>>(x, gate, Wenc, Wdec, benc, bdec, out);
}

// round 12
// speedup vs baseline: 1.5962x; 1.5962x over previous
#include <cuda_runtime.h>

// Problem constants (fixed by the reference)
#define N_SAE  128
#define D_DATA 128
#define D_DICT 512
#define BATCH  1024
#define TB     32     // tokens per MMA batch
#define TCAP   48     // max tokens per expert (mean 16; 8-sigma margin)

typedef unsigned long long u64;
typedef unsigned int u32;

// Cross-CTA combine state (MONOTONIC across graph replays; never reset).
__device__ float g_stage[BATCH * D_DATA];
__device__ int   g_arr  [BATCH];
__device__ int   g_ready[BATCH];

// ---------------- helpers ----------------
__device__ __forceinline__ u64 pk(float lo, float hi) {
    u64 r; asm("mov.b64 %0,{%1,%2};" : "=l"(r) : "f"(lo), "f"(hi)); return r;
}
__device__ __forceinline__ void upk(float& lo, float& hi, u64 v) {
    asm("mov.b64 {%0,%1},%2;" : "=f"(lo), "=f"(hi) : "l"(v));
}
__device__ __forceinline__ u64 add2(u64 a, u64 b) {
    u64 d; asm("add.rn.f32x2 %0,%1,%2;" : "=l"(d) : "l"(a), "l"(b)); return d;
}
__device__ __forceinline__ u32 tf32r(float f) {   // unbiased round-to-nearest tf32
    u32 r; asm("cvt.rna.tf32.f32 %0,%1;" : "=r"(r) : "f"(f)); return r;
}
__device__ __forceinline__ void mma_tf32(float& c0, float& c1, float& c2, float& c3,
                                         u32 a0, u32 a1, u32 a2, u32 a3,
                                         u32 b0, u32 b1) {
    asm("mma.sync.aligned.m16n8k8.row.col.f32.tf32.tf32.f32 "
        "{%0,%1,%2,%3},{%4,%5,%6,%7},{%8,%9},{%0,%1,%2,%3};"
        : "+f"(c0), "+f"(c1), "+f"(c2), "+f"(c3)
        : "r"(a0), "r"(a1), "r"(a2), "r"(a3), "r"(b0), "r"(b1));
}

// Dynamic smem (floats). Row pad 40: LDS bank = (8t+g) mod 32 -> conflict-free
// B fragments. xs[128][40], acts[512][40], part u64[2][16][128].
#define XROW 40
#define OFF_XS   0
#define OFF_ACTS (OFF_XS + D_DATA * XROW)        // 5120
#define OFF_PART (OFF_ACTS + D_DICT * XROW)      // 25600 (u64 region, 4096 u64)
#define SMEM_FLOATS (OFF_PART + 4096 * 2)
#define SMEM_BYTES (SMEM_FLOATS * 4)             // 135168 B (1 CTA/SM)

// ---------------------------------------------------------------------------
// One CTA per expert. grid = 128 (one wave on 148 SMs), 512 threads (16 warps).
// Routing scan -> token list (<=TCAP) -> batches of 32 tokens through
// tf32-MMA encode/decode with weights read ONCE per expert -> lock-free
// cross-CTA combine (monotonic two-arriver protocol).
// ---------------------------------------------------------------------------
__global__ void __launch_bounds__(512, 1)
k_compute(const float* __restrict__ x,
          const float* __restrict__ gate,
          const float* __restrict__ Wenc,
          const float* __restrict__ Wdec,
          const float* __restrict__ benc,
          const float* __restrict__ bdec,
          float* __restrict__ out) {
    int s = blockIdx.x;

    extern __shared__ __align__(16) float smf[];
    float* xs   = smf + OFF_XS;
    float* acts = smf + OFF_ACTS;
    u64*   part = (u64*)(smf + OFF_PART);

    __shared__ float gsf[64];       // gate per rank (zero-padded)
    __shared__ int prtok[64];       // token id per rank
    __shared__ int pj[64];          // pair id (token*2 + j) per rank
    __shared__ int sarr[TB];        // arrival order per batch slot
    __shared__ unsigned masks[32];
    __shared__ int pcnt[32];
    __shared__ int ntot;

    int tid  = threadIdx.x;
    int warp = tid >> 5, lane = tid & 31;
    int g = lane >> 2, t = lane & 3;       // mma fragment coords

    // ---- Routing: column scan of gate[:, s] (proven) ----
    float v0 = __ldg(&gate[(size_t)tid * N_SAE + s]);
    float v1 = __ldg(&gate[(size_t)(tid + 512) * N_SAE + s]);
    unsigned m0 = __ballot_sync(0xffffffffu, v0 != 0.0f);
    unsigned m1 = __ballot_sync(0xffffffffu, v1 != 0.0f);
    if (lane == 0) { masks[warp] = m0; masks[16 + warp] = m1; }
    if (tid < 64) { prtok[tid] = 0; gsf[tid] = 0.0f; pj[tid] = 0; }
    __syncthreads();
    if (warp == 0) {
        int c = __popc(masks[lane]);
        int ex = c;
        #pragma unroll
        for (int o = 1; o < 32; o <<= 1) {
            int tt = __shfl_up_sync(0xffffffffu, ex, o);
            if (lane >= o) ex += tt;
        }
        pcnt[lane] = ex - c;
        if (lane == 31) ntot = ex;
    }
    __syncthreads();
    int n = ntot; if (n > TCAP) n = TCAP;
    if (n == 0) return;

    if (v0 != 0.0f) {
        int r = pcnt[warp] + __popc(m0 & ((1u << lane) - 1));
        if (r < TCAP) { prtok[r] = tid; gsf[r] = v0; }
    }
    if (v1 != 0.0f) {
        int r = pcnt[16 + warp] + __popc(m1 & ((1u << lane) - 1));
        if (r < TCAP) { prtok[r] = tid + 512; gsf[r] = v1; }
    }
    __syncthreads();

    // ---- Slot j per token (pair id): warp row-scans gate[token] ----
    for (int tk = warp; tk < n; tk += 16) {
        int b = prtok[tk];
        float4 gv = ((const float4*)gate)[(size_t)b * (N_SAE / 4) + lane];
        int e0 = lane * 4;
        int c = (gv.x != 0.0f && e0     < s) + (gv.y != 0.0f && e0 + 1 < s)
              + (gv.z != 0.0f && e0 + 2 < s) + (gv.w != 0.0f && e0 + 3 < s);
        #pragma unroll
        for (int o = 16; o > 0; o >>= 1) c += __shfl_xor_sync(0xffffffffu, c, o);
        if (lane == 0) pj[tk] = b * 2 + c;
    }

    // ================= Batch loop (almost always one iteration) =============
    for (int base = 0; base < n; base += TB) {
        int mb = n - base; if (mb > TB) mb = TB;

        // ---- xs[d][slot], tf32-rounded; pad slots -> 0 ----
        for (int i = tid; i < D_DATA * TB; i += 512) {
            int j = i & 31, d = i >> 5;
            float v = (j < mb) ? x[(size_t)prtok[base + j] * D_DATA + d] : 0.0f;
            xs[d * XROW + j] = __uint_as_float(tf32r(v));
        }
        __syncthreads();

        // ---------------- Encode: C[512e x 32tok] ----------------
        {
            int e0 = warp * 32;
            const float* pa = Wenc + (size_t)s * D_DATA * D_DICT + t * D_DICT + e0 + g;
            float c[2][4][4];
            #pragma unroll
            for (int tau = 0; tau < 2; tau++)
                #pragma unroll
                for (int nt = 0; nt < 4; nt++)
                    #pragma unroll
                    for (int q = 0; q < 4; q++) c[tau][nt][q] = 0.0f;

            #pragma unroll 4
            for (int ks = 0; ks < 16; ks++) {
                u32 a00 = tf32r(pa[0]);
                u32 a01 = tf32r(pa[8]);
                u32 a02 = tf32r(pa[4 * D_DICT]);
                u32 a03 = tf32r(pa[4 * D_DICT + 8]);
                u32 a10 = tf32r(pa[16]);
                u32 a11 = tf32r(pa[24]);
                u32 a12 = tf32r(pa[4 * D_DICT + 16]);
                u32 a13 = tf32r(pa[4 * D_DICT + 24]);
                #pragma unroll
                for (int nt = 0; nt < 4; nt++) {
                    u32 b0 = __float_as_uint(xs[(8 * ks + t    ) * XROW + nt * 8 + g]);
                    u32 b1 = __float_as_uint(xs[(8 * ks + t + 4) * XROW + nt * 8 + g]);
                    mma_tf32(c[0][nt][0], c[0][nt][1], c[0][nt][2], c[0][nt][3],
                             a00, a01, a02, a03, b0, b1);
                    mma_tf32(c[1][nt][0], c[1][nt][1], c[1][nt][2], c[1][nt][3],
                             a10, a11, a12, a13, b0, b1);
                }
                pa += 8 * D_DICT;
            }

            // bias + relu + gate + tf32-round -> acts[e][slot]
            #pragma unroll
            for (int tau = 0; tau < 2; tau++) {
                int e = e0 + 16 * tau + g;
                float bg  = benc[(size_t)s * D_DICT + e];
                float bg8 = benc[(size_t)s * D_DICT + e + 8];
                #pragma unroll
                for (int nt = 0; nt < 4; nt++) {
                    int sl = nt * 8 + 2 * t;
                    float gt0 = gsf[base + sl], gt1 = gsf[base + sl + 1];
                    acts[(e    ) * XROW + sl    ] = __uint_as_float(tf32r(fmaxf(c[tau][nt][0] + bg , 0.f) * gt0));
                    acts[(e    ) * XROW + sl + 1] = __uint_as_float(tf32r(fmaxf(c[tau][nt][1] + bg , 0.f) * gt1));
                    acts[(e + 8) * XROW + sl    ] = __uint_as_float(tf32r(fmaxf(c[tau][nt][2] + bg8, 0.f) * gt0));
                    acts[(e + 8) * XROW + sl + 1] = __uint_as_float(tf32r(fmaxf(c[tau][nt][3] + bg8, 0.f) * gt1));
                }
            }
        }
        __syncthreads();

        // ---------------- Decode: C[128d x 32tok] ----------------
        {
            int d0   = (warp & 7) * 16;
            int half = warp >> 3;          // K-half: e in [256*half, 256*half+256)
            const float* pa = Wdec + (size_t)s * D_DICT * D_DATA
                            + (size_t)(half * 256 + t) * D_DATA + d0 + g;
            float c[4][4];
            #pragma unroll
            for (int nt = 0; nt < 4; nt++)
                #pragma unroll
                for (int q = 0; q < 4; q++) c[nt][q] = 0.0f;

            #pragma unroll 4
            for (int ks = 0; ks < 32; ks++) {
                u32 a0 = tf32r(pa[0]);
                u32 a1 = tf32r(pa[8]);
                u32 a2 = tf32r(pa[4 * D_DATA]);
                u32 a3 = tf32r(pa[4 * D_DATA + 8]);
                #pragma unroll
                for (int nt = 0; nt < 4; nt++) {
                    u32 b0 = __float_as_uint(acts[(half * 256 + 8 * ks + t    ) * XROW + nt * 8 + g]);
                    u32 b1 = __float_as_uint(acts[(half * 256 + 8 * ks + t + 4) * XROW + nt * 8 + g]);
                    mma_tf32(c[nt][0], c[nt][1], c[nt][2], c[nt][3],
                             a0, a1, a2, a3, b0, b1);
                }
                pa += 8 * D_DATA;
            }
            #pragma unroll
            for (int nt = 0; nt < 4; nt++) {
                part[half * 2048 + (nt * 4 + t) * 128 + d0 + g    ] = pk(c[nt][0], c[nt][1]);
                part[half * 2048 + (nt * 4 + t) * 128 + d0 + g + 8] = pk(c[nt][2], c[nt][3]);
            }
        }
        __syncthreads();

        // ---- Epilogue: reduce K-halves + b_dec, lock-free combine ----
        {
            int d  = tid & 127;
            int tl = tid >> 7;             // 0..3; token pairs tl+4q
            float bd = bdec[(size_t)s * D_DATA + d];
            float vv[8];
            #pragma unroll
            for (int q = 0; q < 4; q++) {
                int tp = tl + 4 * q;
                u64 sum = add2(part[tp * 128 + d], part[2048 + tp * 128 + d]);
                float lo, hi; upk(lo, hi, sum);
                vv[2 * q] = lo + bd; vv[2 * q + 1] = hi + bd;
            }

            if (tid < TB) sarr[tid] = (tid < mb) ? atomicAdd(&g_arr[prtok[base + tid]], 1) : 0;
            __syncthreads();

            // Phase 1: publish first-role rows (parity 0).
            #pragma unroll
            for (int q = 0; q < 4; q++) {
                #pragma unroll
                for (int r = 0; r < 2; r++) {
                    int j = 2 * (tl + 4 * q) + r;
                    if (j < mb && (sarr[j] & 1) == 0)
                        __stcg(&g_stage[(size_t)prtok[base + j] * D_DATA + d], vv[2 * q + r]);
                }
            }
            __syncthreads();

            if (tid < mb && (sarr[tid] & 1) == 0) {
                __threadfence();
                atomicAdd(&g_ready[prtok[base + tid]], 1);
            }
            // Phase 2: spin (publish-before-spin => no deadlock).
            if (tid < mb && (sarr[tid] & 1) == 1) {
                int b = prtok[base + tid];
                int want = (sarr[tid] >> 1) + 1;
                while (atomicAdd(&g_ready[b], 0) < want) {}
                __threadfence();
            }
            __syncthreads();

            // Phase 3: combine and write final output (second-role tokens).
            #pragma unroll
            for (int q = 0; q < 4; q++) {
                #pragma unroll
                for (int r = 0; r < 2; r++) {
                    int j = 2 * (tl + 4 * q) + r;
                    if (j < mb && (sarr[j] & 1) == 1) {
                        int b = prtok[base + j];
                        float other = __ldcg(&g_stage[(size_t)b * D_DATA + d]);
                        out[(size_t)b * D_DATA + d] = vv[2 * q + r] + other;
                    }
                }
            }
        }
        __syncthreads();   // before next batch reuses xs/acts/part
    }
}

// ---------------------------------------------------------------------------
// Launch. Inputs (metadata order): x, gate, W_enc, W_dec, b_enc, b_dec, k
// ---------------------------------------------------------------------------
extern "C" void kernel_launch(void* const* d_in, const int* in_sizes, int n_in,
                              void* d_out, int out_size) {
    const float* x    = (const float*)d_in[0];
    const float* gate = (const float*)d_in[1];
    const float* Wenc = (const float*)d_in[2];
    const float* Wdec = (const float*)d_in[3];
    const float* benc = (const float*)d_in[4];
    const float* bdec = (const float*)d_in[5];
    float* out = (float*)d_out;

    cudaFuncSetAttribute(k_compute, cudaFuncAttributeMaxDynamicSharedMemorySize,
                         SMEM_BYTES);

    k_compute<<<N_SAE, 512, SMEM_BYTES>>>(x, gate, Wenc, Wdec, benc, bdec, out);
}